// round 14
// baseline (speedup 1.0000x reference)
#include <cuda_runtime.h>
#include <cuda_fp16.h>
#include <stdint.h>

// QLoRALinear: out[128,11008] = x @ dequant_int4(W) + 2*(x@A^T)@B^T
// Round 14: M-split main blocks (64m x 64o x 512k), 4 blocks/SM (32 warps),
// W codes staged via cp.async into raw smem (no register-held W), dequant as
// a pipelined smem->smem pass. KSPLIT=8, same reduce as R12.

#define OUTD 11008
#define IND  4096
#define MTOT 128
#define RLORA 16

#define MH 64                       // m per block
#define NTILE 64                    // o per block
#define KSPLIT 8
#define KC 64                       // k per chunk
#define NCH (IND / KSPLIT / KC)     // 8 chunks per block
#define NGRP (NCH / 2)              // 4 quant groups per slab
#define NCHUNK_TOT (IND / KC)       // 64 tiles in prep layout
#define ROWH 72                     // halves per tile row (64 data + 8 pad)
#define NOTILE (OUTD / NTILE)       // 172

// dynamic smem layout (bytes): two (X fp16 + W fp16) buffers + one raw W buffer
#define XH_OFF 0                    // per-buffer: 64*72*2 = 9216 B
#define WQ_OFF 9216                 // per-buffer: 64*72*2 = 9216 B
#define BUF_B  18432
#define RAW_OFF 36864               // 64*64*4 = 16384 B raw int32 codes
#define SMEM_BYTES (RAW_OFF + 16384)   // 53248 B

// ---- device scratch ----
__device__ __align__(16) uint16_t g_xh[NCHUNK_TOT * MTOT * ROWH];  // fp16 x tiles
__device__ __align__(16) float    g_xa4[4 * MTOT * RLORA];         // xa partial slabs
__device__ float g_partial[KSPLIT * MTOT * OUTD];                  // 45 MB

// ---------------------------------------------------------------------------
__device__ __forceinline__ uint32_t pack_f16x2(float lo, float hi) {
    uint32_t r;
    asm("cvt.rn.f16x2.f32 %0, %1, %2;" : "=r"(r) : "f"(hi), "f"(lo));
    return r;
}
__device__ __forceinline__ uint32_t smem_u32(const void* p) {
    uint32_t a;
    asm("{ .reg .u64 t; cvta.to.shared.u64 t, %1; cvt.u32.u64 %0, t; }"
        : "=r"(a) : "l"(p));
    return a;
}
__device__ __forceinline__ void cp16(uint32_t dst, const void* src) {
    asm volatile("cp.async.cg.shared.global [%0], [%1], 16;"
                 :: "r"(dst), "l"(src) : "memory");
}
__device__ __forceinline__ void mma16816(float* d, const uint32_t* a,
                                         uint32_t b0, uint32_t b1) {
    asm volatile(
        "mma.sync.aligned.m16n8k16.row.col.f32.f16.f16.f32 "
        "{%0,%1,%2,%3}, {%4,%5,%6,%7}, {%8,%9}, {%0,%1,%2,%3};"
        : "+f"(d[0]), "+f"(d[1]), "+f"(d[2]), "+f"(d[3])
        : "r"(a[0]), "r"(a[1]), "r"(a[2]), "r"(a[3]), "r"(b0), "r"(b1));
}
__device__ __forceinline__ void ldm4(uint32_t* r, uint32_t addr) {
    asm volatile("ldmatrix.sync.aligned.m8n8.x4.shared.b16 {%0,%1,%2,%3}, [%4];"
                 : "=r"(r[0]), "=r"(r[1]), "=r"(r[2]), "=r"(r[3]) : "r"(addr));
}

// ---------------------------------------------------------------------------
// Prep: x -> fp16 tile image + xa slab. grid (128, 4), 256 thr. (unchanged)
// ---------------------------------------------------------------------------
__global__ __launch_bounds__(256) void prep_kernel(const float* __restrict__ x,
                                                   const float* __restrict__ A) {
    const int m  = blockIdx.x;
    const int kq = blockIdx.y;
    const int t  = threadIdx.x;
    const int wid = t >> 5, lane = t & 31;
    const int k0 = kq * 1024 + t * 4;

    const float4 xv = *(const float4*)(x + (size_t)m * IND + k0);

    const int chunk = k0 >> 6;
    const int koff  = k0 & 63;
    uint2 hp;
    hp.x = pack_f16x2(xv.x, xv.y);
    hp.y = pack_f16x2(xv.z, xv.w);
    *(uint2*)(g_xh + ((size_t)chunk * MTOT + m) * ROWH + koff) = hp;

    float acc[RLORA];
#pragma unroll
    for (int r = 0; r < RLORA; r++) {
        const float4 a4 = *(const float4*)(A + (size_t)r * IND + k0);
        float s = xv.x * a4.x;
        s = fmaf(xv.y, a4.y, s);
        s = fmaf(xv.z, a4.z, s);
        s = fmaf(xv.w, a4.w, s);
        acc[r] = s;
    }
#pragma unroll
    for (int r = 0; r < RLORA; r++)
#pragma unroll
        for (int off = 16; off > 0; off >>= 1)
            acc[r] += __shfl_xor_sync(0xffffffffu, acc[r], off);

    __shared__ float red[8][RLORA];
    if (lane == 0)
#pragma unroll
        for (int r = 0; r < RLORA; r++) red[wid][r] = acc[r];
    __syncthreads();
    if (t < RLORA) {
        float s = 0.0f;
#pragma unroll
        for (int w = 0; w < 8; w++) s += red[w][t];
        g_xa4[(kq * MTOT + m) * RLORA + t] = s;
    }
}

// ---------------------------------------------------------------------------
// Main GEMM: grid 2752 (172 o-tiles x 8 k-slabs x 2 m-halves), 256 threads,
// 4 blocks/SM. Warp tile 32m x 16o.
// ---------------------------------------------------------------------------
__global__ __launch_bounds__(256, 4) void qmain_kernel(
    const int*   __restrict__ W,
    const int*   __restrict__ zeros,
    const float* __restrict__ scales)
{
    extern __shared__ __align__(16) char smdyn[];
    __shared__ float2 szs[NGRP][NTILE];   // (s, z*s) : 2 KB
    const uint32_t smb = smem_u32(smdyn);

    const int t = threadIdx.x;
    const int lane = t & 31;
    const int wid = t >> 5;
    const int wm = wid & 1;               // 2 x 32m
    const int wo = wid >> 1;              // 4 x 16o

    const int bx = blockIdx.x;
    const int otile = bx >> 4;
    const int kq = (bx >> 1) & 7;
    const int mh = bx & 1;
    const int obase = otile * NTILE;
    const int mbase = mh * MH;
    const int gbase = kq * NGRP;

    // staging maps
    const int so  = t & 63;               // dequant: o lane
    const int skq = t >> 6;               // dequant: 16-k quarter
    const int xrow = t >> 2;              // cpX: m row (0..63)
    const int xseg = t & 3;               // cpX: 16-half segment

    // stage (s, z*s) — 256 entries
    {
        const int g = t >> 6, o = t & 63;
        const float s = scales[(size_t)(gbase + g) * OUTD + obase + o];
        const float z = (float)zeros[(size_t)(gbase + g) * OUTD + obase + o];
        szs[g][o] = make_float2(s, z * s);
    }

    const int rowA = (lane & 7) + ((lane >> 3) & 1) * 8;
    const int kA   = ((lane >> 4) & 1) * 8;
    const int rowB = (lane & 7) + ((lane >> 4) & 1) * 8;
    const int kB   = ((lane >> 3) & 1) * 8;

    float facc[2][2][4];
#pragma unroll
    for (int mt = 0; mt < 2; mt++)
#pragma unroll
        for (int ot = 0; ot < 2; ot++)
#pragma unroll
            for (int i = 0; i < 4; i++) facc[mt][ot][i] = 0.f;

    auto cpX = [&](int b, int c) {
        const int ck = kq * NCH + c;
        const size_t src = ((size_t)ck * MTOT + mbase + xrow) * ROWH + xseg * 16;
        const uint32_t dst = smb + b * BUF_B + XH_OFF + (xrow * ROWH + xseg * 16) * 2;
        cp16(dst, g_xh + src);
        cp16(dst + 16, g_xh + src + 8);
    };
    auto cpWraw = [&](int c) {
        const int ck = kq * NCH + c;
#pragma unroll
        for (int j = 0; j < 4; j++) {
            const int q = t + j * 256;            // 0..1023 16B-chunks
            const int row = q >> 4;
            const int seg = q & 15;
            cp16(smb + RAW_OFF + q * 16,
                 W + (size_t)(ck * KC + row) * OUTD + obase + seg * 4);
        }
    };
    auto dequant = [&](int b, int c) {
        const float2 sz = szs[c >> 1][so];
        const int* raw = (const int*)(smdyn + RAW_OFF);
        uint32_t hp[8];
#pragma unroll
        for (int p = 0; p < 8; p++) {
            const int q0 = raw[(skq * 16 + 2 * p) * 64 + so];
            const int q1 = raw[(skq * 16 + 2 * p + 1) * 64 + so];
            const float f0 = fmaf((float)q0, sz.x, -sz.y);
            const float f1 = fmaf((float)q1, sz.x, -sz.y);
            hp[p] = pack_f16x2(f0, f1);
        }
        uint16_t* wq = (uint16_t*)(smdyn + b * BUF_B + WQ_OFF) + so * ROWH + skq * 16;
        ((uint4*)wq)[0] = make_uint4(hp[0], hp[1], hp[2], hp[3]);
        ((uint4*)wq)[1] = make_uint4(hp[4], hp[5], hp[6], hp[7]);
    };

    __syncthreads();   // szs ready

    // prologue: chunk 0
    cpX(0, 0);
    cpWraw(0);
    asm volatile("cp.async.commit_group;" ::: "memory");
    asm volatile("cp.async.wait_group 0;" ::: "memory");
    __syncthreads();
    dequant(0, 0);

    const int arow = lane >> 2;
    const int acol = (lane & 3) * 2;

    const int aoff0 = XH_OFF / 2 + (wm * 32 + 0 * 16 + rowA) * ROWH + kA;
    const int aoff1 = XH_OFF / 2 + (wm * 32 + 1 * 16 + rowA) * ROWH + kA;
    const int boff  = WQ_OFF / 2 + (wo * 16 + rowB) * ROWH + kB;

    int buf = 0;
#pragma unroll 1
    for (int c = 0; c < NCH; c++) {
        __syncthreads();                       // dequant(c) visible

        if (c + 1 < NCH) {
            cpX(buf ^ 1, c + 1);
            cpWraw(c + 1);
            asm volatile("cp.async.commit_group;" ::: "memory");
        }

        const uint32_t bb = smb + buf * BUF_B;
#pragma unroll
        for (int ks = 0; ks < KC; ks += 16) {
            uint32_t a0[4], a1[4], bq[4];
            ldm4(a0, bb + (aoff0 + ks) * 2);
            ldm4(a1, bb + (aoff1 + ks) * 2);
            ldm4(bq, bb + (boff + ks) * 2);
#pragma unroll
            for (int ot = 0; ot < 2; ot++) {
                mma16816(facc[0][ot], a0, bq[2 * ot], bq[2 * ot + 1]);
                mma16816(facc[1][ot], a1, bq[2 * ot], bq[2 * ot + 1]);
            }
        }

        asm volatile("cp.async.wait_group 0;" ::: "memory");
        __syncthreads();                       // X/raw (c+1) ready, raw free
        if (c + 1 < NCH) dequant(buf ^ 1, c + 1);
        buf ^= 1;
    }

    // ---- store this slab's partial tile (64m x 64o) ----
    float* pp = g_partial + (size_t)kq * MTOT * OUTD;
#pragma unroll
    for (int mt = 0; mt < 2; mt++) {
        const int r0 = mbase + wm * 32 + mt * 16 + arow;
#pragma unroll
        for (int ot = 0; ot < 2; ot++) {
            const int cabs = obase + wo * 16 + ot * 8 + acol;
            *(float2*)&pp[(size_t)r0 * OUTD + cabs] =
                make_float2(facc[mt][ot][0], facc[mt][ot][1]);
            *(float2*)&pp[(size_t)(r0 + 8) * OUTD + cabs] =
                make_float2(facc[mt][ot][2], facc[mt][ot][3]);
        }
    }
}

// ---------------------------------------------------------------------------
// Reduce: 8-way partial sum + LoRA (smem-staged). grid (172, 2), 256 thr.
// ---------------------------------------------------------------------------
__global__ __launch_bounds__(256) void reduce_kernel(
    const float* __restrict__ loraB,
    float*       __restrict__ out)
{
    __shared__ __align__(16) float sB[NTILE][RLORA];    // 4 KB
    __shared__ __align__(16) float sxa[64][RLORA];      // 4 KB

    const int t = threadIdx.x;
    const int obase = blockIdx.x * NTILE;
    const int mbase = blockIdx.y * 64;

    ((float4*)sB)[t] = ((const float4*)(loraB + (size_t)obase * RLORA))[t];
    {
        const int mloc = t >> 2, r4 = t & 3;
        const int fidx = (mbase + mloc) * 4 + r4;
        float4 s0 = ((const float4*)g_xa4)[fidx];
        const float4 s1 = ((const float4*)g_xa4)[fidx + 512];
        const float4 s2 = ((const float4*)g_xa4)[fidx + 1024];
        const float4 s3 = ((const float4*)g_xa4)[fidx + 1536];
        s0.x = 2.0f * (s0.x + s1.x + s2.x + s3.x);
        s0.y = 2.0f * (s0.y + s1.y + s2.y + s3.y);
        s0.z = 2.0f * (s0.z + s1.z + s2.z + s3.z);
        s0.w = 2.0f * (s0.w + s1.w + s2.w + s3.w);
        ((float4*)sxa)[t] = s0;
    }
    __syncthreads();

#pragma unroll
    for (int j = 0; j < 4; j++) {
        const int idx = t + j * 256;
        const int mloc = idx >> 4;
        const int oq = idx & 15;
        const size_t goff = (size_t)(mbase + mloc) * OUTD + obase + oq * 4;

        float4 s = make_float4(0.f, 0.f, 0.f, 0.f);
#pragma unroll
        for (int p = 0; p < KSPLIT; p++) {
            const float4 v = *(const float4*)&g_partial[(size_t)p * MTOT * OUTD + goff];
            s.x += v.x; s.y += v.y; s.z += v.z; s.w += v.w;
        }

        const float* xr = sxa[mloc];
        const int o0 = oq * 4;
        float l[4] = {0.f, 0.f, 0.f, 0.f};
#pragma unroll
        for (int e = 0; e < 4; e++) {
            const float* Bp = sB[o0 + e];
#pragma unroll
            for (int rr = 0; rr < RLORA; rr += 4) {
                const float4 b4 = *(const float4*)(Bp + rr);
                l[e] = fmaf(xr[rr + 0], b4.x, l[e]);
                l[e] = fmaf(xr[rr + 1], b4.y, l[e]);
                l[e] = fmaf(xr[rr + 2], b4.z, l[e]);
                l[e] = fmaf(xr[rr + 3], b4.w, l[e]);
            }
        }
        s.x += l[0]; s.y += l[1]; s.z += l[2]; s.w += l[3];
        *(float4*)&out[goff] = s;
    }
}

// ---------------------------------------------------------------------------
extern "C" void kernel_launch(void* const* d_in, const int* in_sizes, int n_in,
                              void* d_out, int out_size) {
    const float* x      = (const float*)d_in[0];
    const int*   W      = (const int*)  d_in[1];
    const int*   zeros  = (const int*)  d_in[2];
    const float* scales = (const float*)d_in[3];
    const float* loraA  = (const float*)d_in[4];
    const float* loraB  = (const float*)d_in[5];
    float* out = (float*)d_out;

    cudaFuncSetAttribute(qmain_kernel,
                         cudaFuncAttributeMaxDynamicSharedMemorySize, SMEM_BYTES);

    dim3 pgrid(MTOT, 4);
    prep_kernel<<<pgrid, 256>>>(x, loraA);

    qmain_kernel<<<NOTILE * KSPLIT * 2, 256, SMEM_BYTES>>>(W, zeros, scales);

    dim3 rgrid(NOTILE, 2);
    reduce_kernel<<<rgrid, 256>>>(loraB, out);
}

// round 15
// speedup vs baseline: 1.0405x; 1.0405x over previous
#include <cuda_runtime.h>
#include <cuda_fp16.h>
#include <stdint.h>

// QLoRALinear: out[128,11008] = x @ dequant_int4(W) + 2*(x@A^T)@B^T
// Round 15: main kernel = R12 verbatim (best: 92.6us config).
// prep restructured (warp-per-r xa, light blocks), reduce re-tiled (172x4).

#define OUTD 11008
#define IND  4096
#define MTOT 128
#define RLORA 16

#define NTILE 64                    // o per block
#define KSPLIT 8
#define KC 64                       // k per chunk
#define NCH (IND / KSPLIT / KC)     // 8 chunks per block
#define NGRP (NCH / 2)              // 4 quant groups per slab
#define NCHUNK_TOT (IND / KC)       // 64 tiles in prep layout
#define ROWH 72                     // halves per tile row (64 data + 8 pad)
#define NOTILE (OUTD / NTILE)       // 172

// per-buffer smem offsets (halves)
#define XH_OFF 0
#define WQ_OFF 9216                 // 128*72
#define BUF_H  13824                // + 64*72
#define SMEM_BYTES (2 * BUF_H * 2)  // 55296 B dynamic

// ---- device scratch ----
__device__ __align__(16) uint16_t g_xh[NCHUNK_TOT * MTOT * ROWH];  // fp16 x tiles
__device__ __align__(16) float    g_xa8[8 * MTOT * RLORA];         // xa slabs (8 k-slices)
__device__ float g_partial[KSPLIT * MTOT * OUTD];                  // 45 MB

// ---------------------------------------------------------------------------
__device__ __forceinline__ uint32_t pack_f16x2(float lo, float hi) {
    uint32_t r;
    asm("cvt.rn.f16x2.f32 %0, %1, %2;" : "=r"(r) : "f"(hi), "f"(lo));
    return r;
}
__device__ __forceinline__ uint32_t smem_u32(const void* p) {
    uint32_t a;
    asm("{ .reg .u64 t; cvta.to.shared.u64 t, %1; cvt.u32.u64 %0, t; }"
        : "=r"(a) : "l"(p));
    return a;
}
__device__ __forceinline__ void cp16(uint32_t dst, const void* src) {
    asm volatile("cp.async.cg.shared.global [%0], [%1], 16;"
                 :: "r"(dst), "l"(src) : "memory");
}
__device__ __forceinline__ void mma16816(float* d, const uint32_t* a,
                                         uint32_t b0, uint32_t b1) {
    asm volatile(
        "mma.sync.aligned.m16n8k16.row.col.f32.f16.f16.f32 "
        "{%0,%1,%2,%3}, {%4,%5,%6,%7}, {%8,%9}, {%0,%1,%2,%3};"
        : "+f"(d[0]), "+f"(d[1]), "+f"(d[2]), "+f"(d[3])
        : "r"(a[0]), "r"(a[1]), "r"(a[2]), "r"(a[3]), "r"(b0), "r"(b1));
}
__device__ __forceinline__ void ldm4(uint32_t* r, uint32_t addr) {
    asm volatile("ldmatrix.sync.aligned.m8n8.x4.shared.b16 {%0,%1,%2,%3}, [%4];"
                 : "=r"(r[0]), "=r"(r[1]), "=r"(r[2]), "=r"(r[3]) : "r"(addr));
}

// ---------------------------------------------------------------------------
// Prep: grid (128 m, 16 slices), 256 thr.
// slice sl = ks*2 + rh : ks in 0..7 selects 512-k range, rh selects r-half.
//   rh==0 blocks also convert x -> fp16 tile image (2 floats/thread).
//   xa: warp w computes r = rh*8 + w over the 512-k slice (1 shuffle-chain).
// ---------------------------------------------------------------------------
__global__ __launch_bounds__(256) void prep_kernel(const float* __restrict__ x,
                                                   const float* __restrict__ A) {
    const int m  = blockIdx.x;
    const int sl = blockIdx.y;
    const int ks = sl >> 1;
    const int rh = sl & 1;
    const int t  = threadIdx.x;
    const int w  = t >> 5, lane = t & 31;
    const int k0 = ks * 512;

    // conversion (rh==0 blocks): thread t handles k0 + 2t, 2t+1
    if (rh == 0) {
        const int k = k0 + t * 2;
        const float2 xv = *(const float2*)(x + (size_t)m * IND + k);
        const uint32_t h = pack_f16x2(xv.x, xv.y);
        const int chunk = k >> 6;
        const int koff  = k & 63;
        *(uint32_t*)(g_xh + ((size_t)chunk * MTOT + m) * ROWH + koff) = h;
    }

    // xa: warp w -> r = rh*8 + w ; lanes cover 16 k each
    const int r = rh * 8 + w;
    const float* xp = x + (size_t)m * IND + k0 + lane * 16;
    const float* Ap = A + (size_t)r * IND + k0 + lane * 16;
    float acc = 0.0f;
#pragma unroll
    for (int q = 0; q < 4; q++) {
        const float4 xv4 = *(const float4*)(xp + 4 * q);
        const float4 av4 = *(const float4*)(Ap + 4 * q);
        acc = fmaf(xv4.x, av4.x, acc);
        acc = fmaf(xv4.y, av4.y, acc);
        acc = fmaf(xv4.z, av4.z, acc);
        acc = fmaf(xv4.w, av4.w, acc);
    }
#pragma unroll
    for (int off = 16; off > 0; off >>= 1)
        acc += __shfl_xor_sync(0xffffffffu, acc, off);
    if (lane == 0)
        g_xa8[((size_t)ks * MTOT + m) * RLORA + r] = acc;
}

// ---------------------------------------------------------------------------
// Main GEMM (R12 verbatim): grid 1376, 256 threads, 3 blocks/SM.
// ---------------------------------------------------------------------------
__global__ __launch_bounds__(256, 3) void qmain_kernel(
    const int*   __restrict__ W,
    const int*   __restrict__ zeros,
    const float* __restrict__ scales)
{
    extern __shared__ __align__(16) uint16_t smdyn[];
    __shared__ float2 szs[NGRP][NTILE];
    const uint32_t smb = smem_u32(smdyn);

    const int t = threadIdx.x;
    const int lane = t & 31;
    const int wid = t >> 5;
    const int wm = wid & 3;
    const int wo = wid >> 2;
    const int otile = blockIdx.x >> 3;
    const int kq = blockIdx.x & 7;
    const int obase = otile * NTILE;
    const int gbase = kq * NGRP;

    const int so  = t & 63;
    const int skq = t >> 6;
    const int xrow = t >> 1;
    const int xhalf = t & 1;

    {
        const int g = t >> 6, o = t & 63;
        const float s = scales[(size_t)(gbase + g) * OUTD + obase + o];
        const float z = (float)zeros[(size_t)(gbase + g) * OUTD + obase + o];
        szs[g][o] = make_float2(s, z * s);
    }

    const int rowA = (lane & 7) + ((lane >> 3) & 1) * 8;
    const int kA   = ((lane >> 4) & 1) * 8;
    const int rowB = (lane & 7) + ((lane >> 4) & 1) * 8;
    const int kB   = ((lane >> 3) & 1) * 8;

    float facc[2][4][4];
#pragma unroll
    for (int mt = 0; mt < 2; mt++)
#pragma unroll
        for (int ot = 0; ot < 4; ot++)
#pragma unroll
            for (int i = 0; i < 4; i++) facc[mt][ot][i] = 0.f;

    auto cpX = [&](int b, int c) {
        const int ck = kq * NCH + c;
        const size_t src = ((size_t)ck * MTOT + xrow) * ROWH + xhalf * 32;
        const uint32_t dxh = smb + (b * BUF_H + XH_OFF + xrow * ROWH + xhalf * 32) * 2;
#pragma unroll
        for (int j = 0; j < 4; j++)
            cp16(dxh + j * 16, g_xh + src + j * 8);
        asm volatile("cp.async.commit_group;" ::: "memory");
    };
    auto ldgW = [&](int c, int* qv) {
        const int ck = kq * NCH + c;
        const int* Wp = W + (size_t)(ck * KC + skq * 16) * OUTD + obase + so;
#pragma unroll
        for (int p = 0; p < 16; p++) qv[p] = Wp[(size_t)p * OUTD];
    };
    auto stsW = [&](int b, int c, const int* qv) {
        const float2 sz = szs[c >> 1][so];
        uint32_t hp[8];
#pragma unroll
        for (int p = 0; p < 8; p++) {
            const float f0 = fmaf((float)qv[2 * p],     sz.x, -sz.y);
            const float f1 = fmaf((float)qv[2 * p + 1], sz.x, -sz.y);
            hp[p] = pack_f16x2(f0, f1);
        }
        uint16_t* wq = smdyn + b * BUF_H + WQ_OFF + so * ROWH + skq * 16;
        ((uint4*)wq)[0] = make_uint4(hp[0], hp[1], hp[2], hp[3]);
        ((uint4*)wq)[1] = make_uint4(hp[4], hp[5], hp[6], hp[7]);
    };

    __syncthreads();   // szs ready

    int qv[16];
    ldgW(0, qv);
    cpX(0, 0);
    stsW(0, 0, qv);
    asm volatile("cp.async.wait_group 0;" ::: "memory");
    __syncthreads();

    const int arow = lane >> 2;
    const int acol = (lane & 3) * 2;

    const int aoff0 = XH_OFF + (wm * 32 + 0 * 16 + rowA) * ROWH + kA;
    const int aoff1 = XH_OFF + (wm * 32 + 1 * 16 + rowA) * ROWH + kA;
    const int boff0 = WQ_OFF + (wo * 32 + 0 * 16 + rowB) * ROWH + kB;
    const int boff1 = WQ_OFF + (wo * 32 + 1 * 16 + rowB) * ROWH + kB;

    int buf = 0;
#pragma unroll 1
    for (int c = 0; c < NCH; c++) {
        int qn[16];
        if (c + 1 < NCH) {
            ldgW(c + 1, qn);
            cpX(buf ^ 1, c + 1);
        }

        const uint32_t bb = smb + (buf * BUF_H) * 2;
#pragma unroll
        for (int ks = 0; ks < KC; ks += 16) {
            uint32_t a0[4], a1[4], bq0[4], bq1[4];
            ldm4(a0, bb + (aoff0 + ks) * 2);
            ldm4(a1, bb + (aoff1 + ks) * 2);
            ldm4(bq0, bb + (boff0 + ks) * 2);
            ldm4(bq1, bb + (boff1 + ks) * 2);
#pragma unroll
            for (int ot = 0; ot < 4; ot++) {
                const uint32_t b0 = (ot < 2) ? bq0[2 * ot]     : bq1[2 * (ot - 2)];
                const uint32_t b1 = (ot < 2) ? bq0[2 * ot + 1] : bq1[2 * (ot - 2) + 1];
                mma16816(facc[0][ot], a0, b0, b1);
                mma16816(facc[1][ot], a1, b0, b1);
            }
        }

        if (c + 1 < NCH) stsW(buf ^ 1, c + 1, qn);

        asm volatile("cp.async.wait_group 0;" ::: "memory");
        __syncthreads();
        buf ^= 1;
    }

    float* pp = g_partial + (size_t)kq * MTOT * OUTD;
#pragma unroll
    for (int mt = 0; mt < 2; mt++) {
        const int r0 = wm * 32 + mt * 16 + arow;
#pragma unroll
        for (int ot = 0; ot < 4; ot++) {
            const int cabs = obase + wo * 32 + ot * 8 + acol;
            *(float2*)&pp[(size_t)r0 * OUTD + cabs] =
                make_float2(facc[mt][ot][0], facc[mt][ot][1]);
            *(float2*)&pp[(size_t)(r0 + 8) * OUTD + cabs] =
                make_float2(facc[mt][ot][2], facc[mt][ot][3]);
        }
    }
}

// ---------------------------------------------------------------------------
// Reduce: 8-way partial sum + LoRA. grid (172, 4), 256 thr.
// Block covers 64 o x 32 m; 2 float4 outputs per thread.
// ---------------------------------------------------------------------------
__global__ __launch_bounds__(256) void reduce_kernel(
    const float* __restrict__ loraB,
    float*       __restrict__ out)
{
    __shared__ __align__(16) float sB[NTILE][RLORA];    // 4 KB
    __shared__ __align__(16) float sxa[32][RLORA];      // 2 KB

    const int t = threadIdx.x;
    const int obase = blockIdx.x * NTILE;
    const int mbase = blockIdx.y * 32;

    // stage loraB tile (64 o x 16 r) : 256 float4
    ((float4*)sB)[t] = ((const float4*)(loraB + (size_t)obase * RLORA))[t];
    // stage xa for 32 m rows: sum 8 slabs, scale by 2 : 128 float4
    if (t < 128) {
        const int fidx = (mbase + (t >> 2)) * 4 + (t & 3);
        float4 s = ((const float4*)g_xa8)[fidx];
#pragma unroll
        for (int sl = 1; sl < 8; sl++) {
            const float4 v = ((const float4*)g_xa8)[sl * 512 + fidx];
            s.x += v.x; s.y += v.y; s.z += v.z; s.w += v.w;
        }
        s.x *= 2.0f; s.y *= 2.0f; s.z *= 2.0f; s.w *= 2.0f;
        ((float4*)sxa)[t] = s;
    }
    __syncthreads();

    // 32m x 16 float4 = 512 float4; 2 per thread
#pragma unroll
    for (int j = 0; j < 2; j++) {
        const int idx = t + j * 256;
        const int mloc = idx >> 4;
        const int oq = idx & 15;
        const size_t goff = (size_t)(mbase + mloc) * OUTD + obase + oq * 4;

        float4 s = make_float4(0.f, 0.f, 0.f, 0.f);
#pragma unroll
        for (int p = 0; p < KSPLIT; p++) {
            const float4 v = *(const float4*)&g_partial[(size_t)p * MTOT * OUTD + goff];
            s.x += v.x; s.y += v.y; s.z += v.z; s.w += v.w;
        }

        const float* xr = sxa[mloc];
        const int o0 = oq * 4;
        float l[4] = {0.f, 0.f, 0.f, 0.f};
#pragma unroll
        for (int e = 0; e < 4; e++) {
            const float* Bp = sB[o0 + e];
#pragma unroll
            for (int rr = 0; rr < RLORA; rr += 4) {
                const float4 b4 = *(const float4*)(Bp + rr);
                l[e] = fmaf(xr[rr + 0], b4.x, l[e]);
                l[e] = fmaf(xr[rr + 1], b4.y, l[e]);
                l[e] = fmaf(xr[rr + 2], b4.z, l[e]);
                l[e] = fmaf(xr[rr + 3], b4.w, l[e]);
            }
        }
        s.x += l[0]; s.y += l[1]; s.z += l[2]; s.w += l[3];
        *(float4*)&out[goff] = s;
    }
}

// ---------------------------------------------------------------------------
extern "C" void kernel_launch(void* const* d_in, const int* in_sizes, int n_in,
                              void* d_out, int out_size) {
    const float* x      = (const float*)d_in[0];
    const int*   W      = (const int*)  d_in[1];
    const int*   zeros  = (const int*)  d_in[2];
    const float* scales = (const float*)d_in[3];
    const float* loraA  = (const float*)d_in[4];
    const float* loraB  = (const float*)d_in[5];
    float* out = (float*)d_out;

    cudaFuncSetAttribute(qmain_kernel,
                         cudaFuncAttributeMaxDynamicSharedMemorySize, SMEM_BYTES);

    dim3 pgrid(MTOT, 16);
    prep_kernel<<<pgrid, 256>>>(x, loraA);

    qmain_kernel<<<NOTILE * KSPLIT, 256, SMEM_BYTES>>>(W, zeros, scales);

    dim3 rgrid(NOTILE, 4);
    reduce_kernel<<<rgrid, 256>>>(loraB, out);
}

// round 16
// speedup vs baseline: 1.0597x; 1.0185x over previous
#include <cuda_runtime.h>
#include <cuda_fp16.h>
#include <stdint.h>

// QLoRALinear: out[128,11008] = x @ dequant_int4(W) + 2*(x@A^T)@B^T
// Round 16: R12 algorithm with SW128-swizzled smem tiles (48KB/block) and
// half-split W register staging (qn[8]) -> __launch_bounds__(256,4),
// 32 warps/SM. prep + reduce = R12.

#define OUTD 11008
#define IND  4096
#define MTOT 128
#define RLORA 16

#define NTILE 64                    // o per block
#define KSPLIT 8
#define KC 64                       // k per chunk
#define NCH (IND / KSPLIT / KC)     // 8 chunks per block
#define NGRP (NCH / 2)              // 4 quant groups per slab
#define NCHUNK_TOT (IND / KC)       // 64 tiles in prep layout
#define NOTILE (OUTD / NTILE)       // 172

// dynamic smem: per buffer X 16384 B + W 8192 B; two buffers
#define WOFF_B 16384
#define BUF_B  24576
#define SMEM_BYTES (2 * BUF_B)      // 49152 B

// SW128 swizzle within 128B rows: flips bits 4..6 by row&7
#define SWZ(off, row) ((off) ^ (((row) & 7) << 4))

// ---- device scratch ----
// x fp16 tiles, pre-swizzled image: [64 chunks][128 m][128 B]
__device__ __align__(16) uint16_t g_xh[NCHUNK_TOT * MTOT * 64];
__device__ __align__(16) float    g_xa4[4 * MTOT * RLORA];
__device__ float g_partial[KSPLIT * MTOT * OUTD];   // 45 MB

// ---------------------------------------------------------------------------
__device__ __forceinline__ uint32_t pack_f16x2(float lo, float hi) {
    uint32_t r;
    asm("cvt.rn.f16x2.f32 %0, %1, %2;" : "=r"(r) : "f"(hi), "f"(lo));
    return r;
}
__device__ __forceinline__ uint32_t smem_u32(const void* p) {
    uint32_t a;
    asm("{ .reg .u64 t; cvta.to.shared.u64 t, %1; cvt.u32.u64 %0, t; }"
        : "=r"(a) : "l"(p));
    return a;
}
__device__ __forceinline__ void cp16(uint32_t dst, const void* src) {
    asm volatile("cp.async.cg.shared.global [%0], [%1], 16;"
                 :: "r"(dst), "l"(src) : "memory");
}
__device__ __forceinline__ void mma16816(float* d, const uint32_t* a,
                                         uint32_t b0, uint32_t b1) {
    asm volatile(
        "mma.sync.aligned.m16n8k16.row.col.f32.f16.f16.f32 "
        "{%0,%1,%2,%3}, {%4,%5,%6,%7}, {%8,%9}, {%0,%1,%2,%3};"
        : "+f"(d[0]), "+f"(d[1]), "+f"(d[2]), "+f"(d[3])
        : "r"(a[0]), "r"(a[1]), "r"(a[2]), "r"(a[3]), "r"(b0), "r"(b1));
}
__device__ __forceinline__ void ldm4(uint32_t* r, uint32_t addr) {
    asm volatile("ldmatrix.sync.aligned.m8n8.x4.shared.b16 {%0,%1,%2,%3}, [%4];"
                 : "=r"(r[0]), "=r"(r[1]), "=r"(r[2]), "=r"(r[3]) : "r"(addr));
}

// ---------------------------------------------------------------------------
// Prep (R12 form): x -> swizzled fp16 tile image + xa slab. grid (128,4).
// ---------------------------------------------------------------------------
__global__ __launch_bounds__(256) void prep_kernel(const float* __restrict__ x,
                                                   const float* __restrict__ A) {
    const int m  = blockIdx.x;
    const int kq = blockIdx.y;
    const int t  = threadIdx.x;
    const int wid = t >> 5, lane = t & 31;
    const int k0 = kq * 1024 + t * 4;

    const float4 xv = *(const float4*)(x + (size_t)m * IND + k0);

    const int chunk = k0 >> 6;
    const int koff  = k0 & 63;
    uint2 hp;
    hp.x = pack_f16x2(xv.x, xv.y);
    hp.y = pack_f16x2(xv.z, xv.w);
    const uint32_t sw = SWZ((uint32_t)(koff * 2), m);
    *(uint2*)((char*)g_xh + ((size_t)(chunk * MTOT + m) * 128 + sw)) = hp;

    float acc[RLORA];
#pragma unroll
    for (int r = 0; r < RLORA; r++) {
        const float4 a4 = *(const float4*)(A + (size_t)r * IND + k0);
        float s = xv.x * a4.x;
        s = fmaf(xv.y, a4.y, s);
        s = fmaf(xv.z, a4.z, s);
        s = fmaf(xv.w, a4.w, s);
        acc[r] = s;
    }
#pragma unroll
    for (int r = 0; r < RLORA; r++)
#pragma unroll
        for (int off = 16; off > 0; off >>= 1)
            acc[r] += __shfl_xor_sync(0xffffffffu, acc[r], off);

    __shared__ float red[8][RLORA];
    if (lane == 0)
#pragma unroll
        for (int r = 0; r < RLORA; r++) red[wid][r] = acc[r];
    __syncthreads();
    if (t < RLORA) {
        float s = 0.0f;
#pragma unroll
        for (int w = 0; w < 8; w++) s += red[w][t];
        g_xa4[(kq * MTOT + m) * RLORA + t] = s;
    }
}

// ---------------------------------------------------------------------------
// Main GEMM: grid 1376, 256 threads, 4 blocks/SM.
// ---------------------------------------------------------------------------
__global__ __launch_bounds__(256, 4) void qmain_kernel(
    const int*   __restrict__ W,
    const int*   __restrict__ zeros,
    const float* __restrict__ scales)
{
    extern __shared__ __align__(128) char smdyn[];
    __shared__ float2 szs[NGRP][NTILE];
    const uint32_t smb = smem_u32(smdyn);

    const int t = threadIdx.x;
    const int lane = t & 31;
    const int wid = t >> 5;
    const int wm = wid & 3;
    const int wo = wid >> 2;
    const int otile = blockIdx.x >> 3;
    const int kq = blockIdx.x & 7;
    const int obase = otile * NTILE;
    const int gbase = kq * NGRP;

    const int so  = t & 63;
    const int skq = t >> 6;
    const int xrow = t >> 1;
    const int xhalf = t & 1;

    {
        const int g = t >> 6, o = t & 63;
        const float s = scales[(size_t)(gbase + g) * OUTD + obase + o];
        const float z = (float)zeros[(size_t)(gbase + g) * OUTD + obase + o];
        szs[g][o] = make_float2(s, z * s);
    }

    const int rowA = (lane & 7) + ((lane >> 3) & 1) * 8;
    const int kA   = ((lane >> 4) & 1) * 8;
    const int rowB = (lane & 7) + ((lane >> 4) & 1) * 8;
    const int kB   = ((lane >> 3) & 1) * 8;

    float facc[2][4][4];
#pragma unroll
    for (int mt = 0; mt < 2; mt++)
#pragma unroll
        for (int ot = 0; ot < 4; ot++)
#pragma unroll
            for (int i = 0; i < 4; i++) facc[mt][ot][i] = 0.f;

    auto cpX = [&](int b, int c) {
        const int ck = kq * NCH + c;
        const char* src = (const char*)g_xh +
            ((size_t)(ck * MTOT + xrow) * 128 + xhalf * 64);
        const uint32_t dst = smb + b * BUF_B + xrow * 128 + xhalf * 64;
#pragma unroll
        for (int j = 0; j < 4; j++)
            cp16(dst + j * 16, src + j * 16);
        asm volatile("cp.async.commit_group;" ::: "memory");
    };
    // load 8 W rows (half h of this thread's 16-k quarter)
    auto ldgWh = [&](int c, int h, int* qv) {
        const int ck = kq * NCH + c;
        const int* Wp = W + (size_t)(ck * KC + skq * 16 + h * 8) * OUTD + obase + so;
#pragma unroll
        for (int p = 0; p < 8; p++) qv[p] = Wp[(size_t)p * OUTD];
    };
    auto stsWh = [&](int b, int c, int h, const int* qv) {
        const float2 sz = szs[c >> 1][so];
        uint32_t hp[4];
#pragma unroll
        for (int p = 0; p < 4; p++) {
            const float f0 = fmaf((float)qv[2 * p],     sz.x, -sz.y);
            const float f1 = fmaf((float)qv[2 * p + 1], sz.x, -sz.y);
            hp[p] = pack_f16x2(f0, f1);
        }
        const uint32_t col2 = (uint32_t)(skq * 32 + h * 16);
        char* wq = smdyn + b * BUF_B + WOFF_B + so * 128 + SWZ(col2, so);
        *(uint4*)wq = make_uint4(hp[0], hp[1], hp[2], hp[3]);
    };

    __syncthreads();   // szs ready

    // prologue: chunk 0
    {
        int qv[8];
        ldgWh(0, 0, qv);
        stsWh(0, 0, 0, qv);
        ldgWh(0, 1, qv);
        stsWh(0, 0, 1, qv);
        cpX(0, 0);
        asm volatile("cp.async.wait_group 0;" ::: "memory");
        __syncthreads();
    }

    const int arow = lane >> 2;
    const int acol = (lane & 3) * 2;

    // ldmatrix address components (byte offsets within buffer)
    const int rA0 = wm * 32 + rowA;            // m tile rows
    const int rA1 = rA0 + 16;
    const int rB0 = wo * 32 + rowB;            // o tile rows
    const int rB1 = rB0 + 16;
    const uint32_t aBase0 = rA0 * 128, cA0 = (rA0 & 7) << 4;
    const uint32_t aBase1 = rA1 * 128, cA1 = (rA1 & 7) << 4;
    const uint32_t bBase0 = WOFF_B + rB0 * 128, cB0 = (rB0 & 7) << 4;
    const uint32_t bBase1 = WOFF_B + rB1 * 128, cB1 = (rB1 & 7) << 4;
    const uint32_t inA = kA * 2;               // byte offset of k fragment
    const uint32_t inB = kB * 2;

    int buf = 0;
    int qv[8];
#pragma unroll 1
    for (int c = 0; c < NCH; c++) {
        const uint32_t bb = smb + buf * BUF_B;

        if (c + 1 < NCH) {
            cpX(buf ^ 1, c + 1);
            ldgWh(c + 1, 0, qv);
        }

        // ---- first half: ks = 0, 16 ----
#pragma unroll
        for (int ks = 0; ks < 32; ks += 16) {
            const uint32_t k2 = ks * 2;
            uint32_t a0[4], a1[4], bq0[4], bq1[4];
            ldm4(a0, bb + aBase0 + ((inA + k2) ^ cA0));
            ldm4(a1, bb + aBase1 + ((inA + k2) ^ cA1));
            ldm4(bq0, bb + bBase0 + ((inB + k2) ^ cB0));
            ldm4(bq1, bb + bBase1 + ((inB + k2) ^ cB1));
#pragma unroll
            for (int ot = 0; ot < 4; ot++) {
                const uint32_t b0 = (ot < 2) ? bq0[2 * ot]     : bq1[2 * (ot - 2)];
                const uint32_t b1 = (ot < 2) ? bq0[2 * ot + 1] : bq1[2 * (ot - 2) + 1];
                mma16816(facc[0][ot], a0, b0, b1);
                mma16816(facc[1][ot], a1, b0, b1);
            }
        }

        if (c + 1 < NCH) {
            stsWh(buf ^ 1, c + 1, 0, qv);
            ldgWh(c + 1, 1, qv);
        }

        // ---- second half: ks = 32, 48 ----
#pragma unroll
        for (int ks = 32; ks < 64; ks += 16) {
            const uint32_t k2 = ks * 2;
            uint32_t a0[4], a1[4], bq0[4], bq1[4];
            ldm4(a0, bb + aBase0 + ((inA + k2) ^ cA0));
            ldm4(a1, bb + aBase1 + ((inA + k2) ^ cA1));
            ldm4(bq0, bb + bBase0 + ((inB + k2) ^ cB0));
            ldm4(bq1, bb + bBase1 + ((inB + k2) ^ cB1));
#pragma unroll
            for (int ot = 0; ot < 4; ot++) {
                const uint32_t b0 = (ot < 2) ? bq0[2 * ot]     : bq1[2 * (ot - 2)];
                const uint32_t b1 = (ot < 2) ? bq0[2 * ot + 1] : bq1[2 * (ot - 2) + 1];
                mma16816(facc[0][ot], a0, b0, b1);
                mma16816(facc[1][ot], a1, b0, b1);
            }
        }

        if (c + 1 < NCH) stsWh(buf ^ 1, c + 1, 1, qv);

        asm volatile("cp.async.wait_group 0;" ::: "memory");
        __syncthreads();
        buf ^= 1;
    }

    // ---- store this slab's partial tile ----
    float* pp = g_partial + (size_t)kq * MTOT * OUTD;
#pragma unroll
    for (int mt = 0; mt < 2; mt++) {
        const int r0 = wm * 32 + mt * 16 + arow;
#pragma unroll
        for (int ot = 0; ot < 4; ot++) {
            const int cabs = obase + wo * 32 + ot * 8 + acol;
            *(float2*)&pp[(size_t)r0 * OUTD + cabs] =
                make_float2(facc[mt][ot][0], facc[mt][ot][1]);
            *(float2*)&pp[(size_t)(r0 + 8) * OUTD + cabs] =
                make_float2(facc[mt][ot][2], facc[mt][ot][3]);
        }
    }
}

// ---------------------------------------------------------------------------
// Reduce (R12 form): 8-way partial sum + LoRA. grid (172, 2), 256 thr.
// ---------------------------------------------------------------------------
__global__ __launch_bounds__(256) void reduce_kernel(
    const float* __restrict__ loraB,
    float*       __restrict__ out)
{
    __shared__ __align__(16) float sB[NTILE][RLORA];
    __shared__ __align__(16) float sxa[64][RLORA];

    const int t = threadIdx.x;
    const int obase = blockIdx.x * NTILE;
    const int mbase = blockIdx.y * 64;

    ((float4*)sB)[t] = ((const float4*)(loraB + (size_t)obase * RLORA))[t];
    {
        const int mloc = t >> 2, r4 = t & 3;
        const int fidx = (mbase + mloc) * 4 + r4;
        float4 s0 = ((const float4*)g_xa4)[fidx];
        const float4 s1 = ((const float4*)g_xa4)[fidx + 512];
        const float4 s2 = ((const float4*)g_xa4)[fidx + 1024];
        const float4 s3 = ((const float4*)g_xa4)[fidx + 1536];
        s0.x = 2.0f * (s0.x + s1.x + s2.x + s3.x);
        s0.y = 2.0f * (s0.y + s1.y + s2.y + s3.y);
        s0.z = 2.0f * (s0.z + s1.z + s2.z + s3.z);
        s0.w = 2.0f * (s0.w + s1.w + s2.w + s3.w);
        ((float4*)sxa)[t] = s0;
    }
    __syncthreads();

#pragma unroll
    for (int j = 0; j < 4; j++) {
        const int idx = t + j * 256;
        const int mloc = idx >> 4;
        const int oq = idx & 15;
        const size_t goff = (size_t)(mbase + mloc) * OUTD + obase + oq * 4;

        float4 s = make_float4(0.f, 0.f, 0.f, 0.f);
#pragma unroll
        for (int p = 0; p < KSPLIT; p++) {
            const float4 v = *(const float4*)&g_partial[(size_t)p * MTOT * OUTD + goff];
            s.x += v.x; s.y += v.y; s.z += v.z; s.w += v.w;
        }

        const float* xr = sxa[mloc];
        const int o0 = oq * 4;
        float l[4] = {0.f, 0.f, 0.f, 0.f};
#pragma unroll
        for (int e = 0; e < 4; e++) {
            const float* Bp = sB[o0 + e];
#pragma unroll
            for (int rr = 0; rr < RLORA; rr += 4) {
                const float4 b4 = *(const float4*)(Bp + rr);
                l[e] = fmaf(xr[rr + 0], b4.x, l[e]);
                l[e] = fmaf(xr[rr + 1], b4.y, l[e]);
                l[e] = fmaf(xr[rr + 2], b4.z, l[e]);
                l[e] = fmaf(xr[rr + 3], b4.w, l[e]);
            }
        }
        s.x += l[0]; s.y += l[1]; s.z += l[2]; s.w += l[3];
        *(float4*)&out[goff] = s;
    }
}

// ---------------------------------------------------------------------------
extern "C" void kernel_launch(void* const* d_in, const int* in_sizes, int n_in,
                              void* d_out, int out_size) {
    const float* x      = (const float*)d_in[0];
    const int*   W      = (const int*)  d_in[1];
    const int*   zeros  = (const int*)  d_in[2];
    const float* scales = (const float*)d_in[3];
    const float* loraA  = (const float*)d_in[4];
    const float* loraB  = (const float*)d_in[5];
    float* out = (float*)d_out;

    cudaFuncSetAttribute(qmain_kernel,
                         cudaFuncAttributeMaxDynamicSharedMemorySize, SMEM_BYTES);

    dim3 pgrid(MTOT, 4);
    prep_kernel<<<pgrid, 256>>>(x, loraA);

    qmain_kernel<<<NOTILE * KSPLIT, 256, SMEM_BYTES>>>(W, zeros, scales);

    dim3 rgrid(NOTILE, 2);
    reduce_kernel<<<rgrid, 256>>>(loraB, out);
}

// round 17
// speedup vs baseline: 1.1504x; 1.0856x over previous
#include <cuda_runtime.h>
#include <cuda_fp16.h>
#include <stdint.h>

// QLoRALinear: out[128,11008] = x @ dequant_int4(W) + 2*(x@A^T)@B^T
// Round 17: R12 (best, 92.6us) with ONE change: k-split partials stored as
// fp16 (half2) instead of fp32 -> partial traffic halved (45MB -> 22.5MB).
// Error model: +3e-4 RMS from partial rounding, combined ~4.2e-4 < 1e-3.

#define OUTD 11008
#define IND  4096
#define MTOT 128
#define RLORA 16

#define NTILE 64                    // o per block
#define KSPLIT 8
#define KC 64                       // k per chunk
#define NCH (IND / KSPLIT / KC)     // 8 chunks per block
#define NGRP (NCH / 2)              // 4 quant groups per slab
#define NCHUNK_TOT (IND / KC)       // 64 tiles in prep layout
#define ROWH 72                     // halves per tile row (64 data + 8 pad)
#define NOTILE (OUTD / NTILE)       // 172

// per-buffer smem offsets (halves)
#define XH_OFF 0
#define WQ_OFF 9216                 // 128*72
#define BUF_H  13824                // + 64*72
#define SMEM_BYTES (2 * BUF_H * 2)  // 55296 B dynamic

// ---- device scratch ----
__device__ __align__(16) uint16_t g_xh[NCHUNK_TOT * MTOT * ROWH];  // fp16 x tiles
__device__ __align__(16) float    g_xa4[4 * MTOT * RLORA];         // xa partial slabs
__device__ __align__(16) __half   g_ph[KSPLIT * MTOT * OUTD];      // fp16 partials, 22.5 MB

// ---------------------------------------------------------------------------
__device__ __forceinline__ uint32_t pack_f16x2(float lo, float hi) {
    uint32_t r;
    asm("cvt.rn.f16x2.f32 %0, %1, %2;" : "=r"(r) : "f"(hi), "f"(lo));
    return r;
}
__device__ __forceinline__ uint32_t smem_u32(const void* p) {
    uint32_t a;
    asm("{ .reg .u64 t; cvta.to.shared.u64 t, %1; cvt.u32.u64 %0, t; }"
        : "=r"(a) : "l"(p));
    return a;
}
__device__ __forceinline__ void cp16(uint32_t dst, const void* src) {
    asm volatile("cp.async.cg.shared.global [%0], [%1], 16;"
                 :: "r"(dst), "l"(src) : "memory");
}
__device__ __forceinline__ void mma16816(float* d, const uint32_t* a,
                                         uint32_t b0, uint32_t b1) {
    asm volatile(
        "mma.sync.aligned.m16n8k16.row.col.f32.f16.f16.f32 "
        "{%0,%1,%2,%3}, {%4,%5,%6,%7}, {%8,%9}, {%0,%1,%2,%3};"
        : "+f"(d[0]), "+f"(d[1]), "+f"(d[2]), "+f"(d[3])
        : "r"(a[0]), "r"(a[1]), "r"(a[2]), "r"(a[3]), "r"(b0), "r"(b1));
}
__device__ __forceinline__ void ldm4(uint32_t* r, uint32_t addr) {
    asm volatile("ldmatrix.sync.aligned.m8n8.x4.shared.b16 {%0,%1,%2,%3}, [%4];"
                 : "=r"(r[0]), "=r"(r[1]), "=r"(r[2]), "=r"(r[3]) : "r"(addr));
}

// ---------------------------------------------------------------------------
// Prep (R12 verbatim): x -> fp16 tile image + xa slab. grid (128, 4), 256 thr.
// ---------------------------------------------------------------------------
__global__ __launch_bounds__(256) void prep_kernel(const float* __restrict__ x,
                                                   const float* __restrict__ A) {
    const int m  = blockIdx.x;
    const int kq = blockIdx.y;
    const int t  = threadIdx.x;
    const int wid = t >> 5, lane = t & 31;
    const int k0 = kq * 1024 + t * 4;

    const float4 xv = *(const float4*)(x + (size_t)m * IND + k0);

    const int chunk = k0 >> 6;
    const int koff  = k0 & 63;
    uint2 hp;
    hp.x = pack_f16x2(xv.x, xv.y);
    hp.y = pack_f16x2(xv.z, xv.w);
    *(uint2*)(g_xh + ((size_t)chunk * MTOT + m) * ROWH + koff) = hp;

    float acc[RLORA];
#pragma unroll
    for (int r = 0; r < RLORA; r++) {
        const float4 a4 = *(const float4*)(A + (size_t)r * IND + k0);
        float s = xv.x * a4.x;
        s = fmaf(xv.y, a4.y, s);
        s = fmaf(xv.z, a4.z, s);
        s = fmaf(xv.w, a4.w, s);
        acc[r] = s;
    }
#pragma unroll
    for (int r = 0; r < RLORA; r++)
#pragma unroll
        for (int off = 16; off > 0; off >>= 1)
            acc[r] += __shfl_xor_sync(0xffffffffu, acc[r], off);

    __shared__ float red[8][RLORA];
    if (lane == 0)
#pragma unroll
        for (int r = 0; r < RLORA; r++) red[wid][r] = acc[r];
    __syncthreads();
    if (t < RLORA) {
        float s = 0.0f;
#pragma unroll
        for (int w = 0; w < 8; w++) s += red[w][t];
        g_xa4[(kq * MTOT + m) * RLORA + t] = s;
    }
}

// ---------------------------------------------------------------------------
// Main GEMM (R12 verbatim except half2 partial store): grid 1376, 256 thr,
// 3 blocks/SM.
// ---------------------------------------------------------------------------
__global__ __launch_bounds__(256, 3) void qmain_kernel(
    const int*   __restrict__ W,
    const int*   __restrict__ zeros,
    const float* __restrict__ scales)
{
    extern __shared__ __align__(16) uint16_t smdyn[];
    __shared__ float2 szs[NGRP][NTILE];
    const uint32_t smb = smem_u32(smdyn);

    const int t = threadIdx.x;
    const int lane = t & 31;
    const int wid = t >> 5;
    const int wm = wid & 3;
    const int wo = wid >> 2;
    const int otile = blockIdx.x >> 3;
    const int kq = blockIdx.x & 7;
    const int obase = otile * NTILE;
    const int gbase = kq * NGRP;

    const int so  = t & 63;
    const int skq = t >> 6;
    const int xrow = t >> 1;
    const int xhalf = t & 1;

    {
        const int g = t >> 6, o = t & 63;
        const float s = scales[(size_t)(gbase + g) * OUTD + obase + o];
        const float z = (float)zeros[(size_t)(gbase + g) * OUTD + obase + o];
        szs[g][o] = make_float2(s, z * s);
    }

    const int rowA = (lane & 7) + ((lane >> 3) & 1) * 8;
    const int kA   = ((lane >> 4) & 1) * 8;
    const int rowB = (lane & 7) + ((lane >> 4) & 1) * 8;
    const int kB   = ((lane >> 3) & 1) * 8;

    float facc[2][4][4];
#pragma unroll
    for (int mt = 0; mt < 2; mt++)
#pragma unroll
        for (int ot = 0; ot < 4; ot++)
#pragma unroll
            for (int i = 0; i < 4; i++) facc[mt][ot][i] = 0.f;

    auto cpX = [&](int b, int c) {
        const int ck = kq * NCH + c;
        const size_t src = ((size_t)ck * MTOT + xrow) * ROWH + xhalf * 32;
        const uint32_t dxh = smb + (b * BUF_H + XH_OFF + xrow * ROWH + xhalf * 32) * 2;
#pragma unroll
        for (int j = 0; j < 4; j++)
            cp16(dxh + j * 16, g_xh + src + j * 8);
        asm volatile("cp.async.commit_group;" ::: "memory");
    };
    auto ldgW = [&](int c, int* qv) {
        const int ck = kq * NCH + c;
        const int* Wp = W + (size_t)(ck * KC + skq * 16) * OUTD + obase + so;
#pragma unroll
        for (int p = 0; p < 16; p++) qv[p] = Wp[(size_t)p * OUTD];
    };
    auto stsW = [&](int b, int c, const int* qv) {
        const float2 sz = szs[c >> 1][so];
        uint32_t hp[8];
#pragma unroll
        for (int p = 0; p < 8; p++) {
            const float f0 = fmaf((float)qv[2 * p],     sz.x, -sz.y);
            const float f1 = fmaf((float)qv[2 * p + 1], sz.x, -sz.y);
            hp[p] = pack_f16x2(f0, f1);
        }
        uint16_t* wq = smdyn + b * BUF_H + WQ_OFF + so * ROWH + skq * 16;
        ((uint4*)wq)[0] = make_uint4(hp[0], hp[1], hp[2], hp[3]);
        ((uint4*)wq)[1] = make_uint4(hp[4], hp[5], hp[6], hp[7]);
    };

    __syncthreads();   // szs ready

    int qv[16];
    ldgW(0, qv);
    cpX(0, 0);
    stsW(0, 0, qv);
    asm volatile("cp.async.wait_group 0;" ::: "memory");
    __syncthreads();

    const int arow = lane >> 2;
    const int acol = (lane & 3) * 2;

    const int aoff0 = XH_OFF + (wm * 32 + 0 * 16 + rowA) * ROWH + kA;
    const int aoff1 = XH_OFF + (wm * 32 + 1 * 16 + rowA) * ROWH + kA;
    const int boff0 = WQ_OFF + (wo * 32 + 0 * 16 + rowB) * ROWH + kB;
    const int boff1 = WQ_OFF + (wo * 32 + 1 * 16 + rowB) * ROWH + kB;

    int buf = 0;
#pragma unroll 1
    for (int c = 0; c < NCH; c++) {
        int qn[16];
        if (c + 1 < NCH) {
            ldgW(c + 1, qn);
            cpX(buf ^ 1, c + 1);
        }

        const uint32_t bb = smb + (buf * BUF_H) * 2;
#pragma unroll
        for (int ks = 0; ks < KC; ks += 16) {
            uint32_t a0[4], a1[4], bq0[4], bq1[4];
            ldm4(a0, bb + (aoff0 + ks) * 2);
            ldm4(a1, bb + (aoff1 + ks) * 2);
            ldm4(bq0, bb + (boff0 + ks) * 2);
            ldm4(bq1, bb + (boff1 + ks) * 2);
#pragma unroll
            for (int ot = 0; ot < 4; ot++) {
                const uint32_t b0 = (ot < 2) ? bq0[2 * ot]     : bq1[2 * (ot - 2)];
                const uint32_t b1 = (ot < 2) ? bq0[2 * ot + 1] : bq1[2 * (ot - 2) + 1];
                mma16816(facc[0][ot], a0, b0, b1);
                mma16816(facc[1][ot], a1, b0, b1);
            }
        }

        if (c + 1 < NCH) stsW(buf ^ 1, c + 1, qn);

        asm volatile("cp.async.wait_group 0;" ::: "memory");
        __syncthreads();
        buf ^= 1;
    }

    // ---- store this slab's partial tile as fp16 ----
    __half* pp = g_ph + (size_t)kq * MTOT * OUTD;
#pragma unroll
    for (int mt = 0; mt < 2; mt++) {
        const int r0 = wm * 32 + mt * 16 + arow;
#pragma unroll
        for (int ot = 0; ot < 4; ot++) {
            const int cabs = obase + wo * 32 + ot * 8 + acol;
            *(uint32_t*)&pp[(size_t)r0 * OUTD + cabs] =
                pack_f16x2(facc[mt][ot][0], facc[mt][ot][1]);
            *(uint32_t*)&pp[(size_t)(r0 + 8) * OUTD + cabs] =
                pack_f16x2(facc[mt][ot][2], facc[mt][ot][3]);
        }
    }
}

// ---------------------------------------------------------------------------
// Reduce (R12 form, half partials): 8-way sum + LoRA. grid (172, 2), 256 thr.
// ---------------------------------------------------------------------------
__global__ __launch_bounds__(256) void reduce_kernel(
    const float* __restrict__ loraB,
    float*       __restrict__ out)
{
    __shared__ __align__(16) float sB[NTILE][RLORA];
    __shared__ __align__(16) float sxa[64][RLORA];

    const int t = threadIdx.x;
    const int obase = blockIdx.x * NTILE;
    const int mbase = blockIdx.y * 64;

    ((float4*)sB)[t] = ((const float4*)(loraB + (size_t)obase * RLORA))[t];
    {
        const int mloc = t >> 2, r4 = t & 3;
        const int fidx = (mbase + mloc) * 4 + r4;
        float4 s0 = ((const float4*)g_xa4)[fidx];
        const float4 s1 = ((const float4*)g_xa4)[fidx + 512];
        const float4 s2 = ((const float4*)g_xa4)[fidx + 1024];
        const float4 s3 = ((const float4*)g_xa4)[fidx + 1536];
        s0.x = 2.0f * (s0.x + s1.x + s2.x + s3.x);
        s0.y = 2.0f * (s0.y + s1.y + s2.y + s3.y);
        s0.z = 2.0f * (s0.z + s1.z + s2.z + s3.z);
        s0.w = 2.0f * (s0.w + s1.w + s2.w + s3.w);
        ((float4*)sxa)[t] = s0;
    }
    __syncthreads();

#pragma unroll
    for (int j = 0; j < 4; j++) {
        const int idx = t + j * 256;
        const int mloc = idx >> 4;
        const int oq = idx & 15;
        const size_t goff = (size_t)(mbase + mloc) * OUTD + obase + oq * 4;

        float4 s = make_float4(0.f, 0.f, 0.f, 0.f);
#pragma unroll
        for (int p = 0; p < KSPLIT; p++) {
            const uint2 raw = *(const uint2*)&g_ph[(size_t)p * MTOT * OUTD + goff];
            const float2 v01 = __half22float2(*(const __half2*)&raw.x);
            const float2 v23 = __half22float2(*(const __half2*)&raw.y);
            s.x += v01.x; s.y += v01.y; s.z += v23.x; s.w += v23.y;
        }

        const float* xr = sxa[mloc];
        const int o0 = oq * 4;
        float l[4] = {0.f, 0.f, 0.f, 0.f};
#pragma unroll
        for (int e = 0; e < 4; e++) {
            const float* Bp = sB[o0 + e];
#pragma unroll
            for (int rr = 0; rr < RLORA; rr += 4) {
                const float4 b4 = *(const float4*)(Bp + rr);
                l[e] = fmaf(xr[rr + 0], b4.x, l[e]);
                l[e] = fmaf(xr[rr + 1], b4.y, l[e]);
                l[e] = fmaf(xr[rr + 2], b4.z, l[e]);
                l[e] = fmaf(xr[rr + 3], b4.w, l[e]);
            }
        }
        s.x += l[0]; s.y += l[1]; s.z += l[2]; s.w += l[3];
        *(float4*)&out[goff] = s;
    }
}

// ---------------------------------------------------------------------------
extern "C" void kernel_launch(void* const* d_in, const int* in_sizes, int n_in,
                              void* d_out, int out_size) {
    const float* x      = (const float*)d_in[0];
    const int*   W      = (const int*)  d_in[1];
    const int*   zeros  = (const int*)  d_in[2];
    const float* scales = (const float*)d_in[3];
    const float* loraA  = (const float*)d_in[4];
    const float* loraB  = (const float*)d_in[5];
    float* out = (float*)d_out;

    cudaFuncSetAttribute(qmain_kernel,
                         cudaFuncAttributeMaxDynamicSharedMemorySize, SMEM_BYTES);

    dim3 pgrid(MTOT, 4);
    prep_kernel<<<pgrid, 256>>>(x, loraA);

    qmain_kernel<<<NOTILE * KSPLIT, 256, SMEM_BYTES>>>(W, zeros, scales);

    dim3 rgrid(NOTILE, 2);
    reduce_kernel<<<rgrid, 256>>>(loraB, out);
}